// round 5
// baseline (speedup 1.0000x reference)
#include <cuda_runtime.h>
#include <cuda_bf16.h>
#include <cstddef>

#define DIM1 100000
#define DIM2 100000
#define RANK 64
#define BATCH 262144

// Transposed factor tables in bf16, (DIM, 64) row-major: each row = 128B.
// uint4 arrays guarantee 16B alignment. DIM*64 bf16 = DIM*8 uint4.
__device__ uint4 g_UTh[(size_t)DIM1 * 8];
__device__ uint4 g_VTh[(size_t)DIM2 * 8];
__device__ int   g_x_is_i64;   // 1 if x is int64 (lo/hi pairs), 0 if int32

// ---------------------------------------------------------------------------
// Kernel 1: transpose + fp32->bf16 convert. (64 x DIM) -> (DIM x 64) bf16.
// Tile: 64 ranks x 32 dim-cols. Block (32,16): 4 coalesced loads per thread,
// warp-wide 128B-row bf16x2 stores. blockIdx.z selects U/V. Thread 0 of
// block 0 also probes the x dtype (int64 => all odd 32-bit words are 0).
// ---------------------------------------------------------------------------
__global__ void __launch_bounds__(512)
transpose_convert_kernel(const float* __restrict__ U_w,
                         const float* __restrict__ V_w,
                         const int* __restrict__ xw) {
    __shared__ float tile[64][33];

    if (blockIdx.x == 0 && blockIdx.z == 0 &&
        threadIdx.x == 0 && threadIdx.y == 0) {
        int all_zero = 1;
        #pragma unroll
        for (int k = 0; k < 32; ++k)
            if (xw[2 * k + 1] != 0) all_zero = 0;
        g_x_is_i64 = all_zero;
    }

    const float*      src = (blockIdx.z == 0) ? U_w : V_w;
    __nv_bfloat162*   dst = (__nv_bfloat162*)((blockIdx.z == 0) ? g_UTh : g_VTh);

    int c0 = blockIdx.x * 32;                 // DIM offset; DIM1 % 32 == 0
    int tx = threadIdx.x, ty = threadIdx.y;

    #pragma unroll
    for (int j = 0; j < 4; ++j) {
        int r = ty + 16 * j;                  // 0..63
        tile[r][tx] = src[(size_t)r * DIM1 + (c0 + tx)];
    }
    __syncthreads();

    #pragma unroll
    for (int j = 0; j < 2; ++j) {
        int c = ty + 16 * j;                  // 0..31
        float lo = tile[2 * tx][c];
        float hi = tile[2 * tx + 1][c];
        dst[(size_t)(c0 + c) * 32 + tx] = __floats2bfloat162_rn(lo, hi);
    }
}

// 8-term bf16 dot accumulated in fp32.
__device__ __forceinline__ float dot8(uint4 a, uint4 b) {
    const __nv_bfloat162* pa = (const __nv_bfloat162*)&a;
    const __nv_bfloat162* pb = (const __nv_bfloat162*)&b;
    float s = 0.0f;
    #pragma unroll
    for (int k = 0; k < 4; ++k) {
        float2 fa = __bfloat1622float2(pa[k]);
        float2 fb = __bfloat1622float2(pb[k]);
        s += fa.x * fb.x + fa.y * fb.y;
    }
    return s;
}

// ---------------------------------------------------------------------------
// Kernel 2: gather + rank-64 dot. 2 lanes per batch element; each lane loads
// 4 consecutive uint4 (64B) from each 128B table row -> 8 independent table
// loads per thread (MLP 8) plus one index load and one bias load. Shfl
// depth 1; biases on lanes 0/1 ride the reduction.
// ---------------------------------------------------------------------------
__global__ void __launch_bounds__(256)
gather_dot_kernel(const int* __restrict__ xw,
                  const float* __restrict__ bias_U,
                  const float* __restrict__ bias_V,
                  float* __restrict__ out) {
    int gid  = blockIdx.x * blockDim.x + threadIdx.x;
    int b    = gid >> 1;        // 2 lanes per element
    int lane = gid & 1;
    if (b >= BATCH) return;

    int i1, i2;
    if (g_x_is_i64) {           // int64 pairs: one 16B load covers both
        int4 p = __ldg((const int4*)xw + b);
        i1 = p.x;
        i2 = p.z;
    } else {                    // int32 pairs
        int2 p = __ldg((const int2*)xw + b);
        i1 = p.x;
        i2 = p.y;
    }

    const uint4* u = g_UTh + (size_t)i1 * 8 + 4 * lane;
    const uint4* v = g_VTh + (size_t)i2 * 8 + 4 * lane;

    // 8 independent 16B loads + bias: deep MLP.
    uint4 a0 = __ldg(u);
    uint4 a1 = __ldg(u + 1);
    uint4 a2 = __ldg(u + 2);
    uint4 a3 = __ldg(u + 3);
    uint4 c0 = __ldg(v);
    uint4 c1 = __ldg(v + 1);
    uint4 c2 = __ldg(v + 2);
    uint4 c3 = __ldg(v + 3);

    float bias = (lane == 0) ? __ldg(bias_U + i1) : __ldg(bias_V + i2);

    float s = dot8(a0, c0) + dot8(a1, c1) + dot8(a2, c2) + dot8(a3, c3) + bias;

    // Reduce across the 2-lane group (biases ride along).
    s += __shfl_xor_sync(0xffffffffu, s, 1);

    if (lane == 0) out[b] = s;
}

// ---------------------------------------------------------------------------
// kernel_launch: transpose+convert (+probe), then gather. Two launches,
// no sync, no allocation, graph-capturable.
// Input order: x, U_w(f32, RANK*DIM1), V_w(f32, RANK*DIM2), bias_U, bias_V
// ---------------------------------------------------------------------------
extern "C" void kernel_launch(void* const* d_in, const int* in_sizes, int n_in,
                              void* d_out, int out_size) {
    const int*   xw     = (const int*)d_in[0];
    const float* U_w    = (const float*)d_in[1];
    const float* V_w    = (const float*)d_in[2];
    const float* bias_U = (const float*)d_in[3];
    const float* bias_V = (const float*)d_in[4];
    float*       out    = (float*)d_out;

    dim3 tgrid(DIM1 / 32, 1, 2);
    dim3 tblock(32, 16, 1);
    transpose_convert_kernel<<<tgrid, tblock>>>(U_w, V_w, xw);

    int total_threads = BATCH * 2;
    int block = 256;
    int grid  = (total_threads + block - 1) / block;
    gather_dot_kernel<<<grid, block>>>(xw, bias_U, bias_V, out);
}

// round 7
// speedup vs baseline: 1.1538x; 1.1538x over previous
#include <cuda_runtime.h>
#include <cuda_bf16.h>
#include <cstddef>

#define DIM1 100000
#define DIM2 100000
#define RANK 64
#define BATCH 262144

// Transposed factor tables in bf16, (DIM, 64) row-major: each row = 128B.
// uint4 arrays guarantee 16B alignment. DIM*64 bf16 = DIM*8 uint4.
__device__ uint4 g_UTh[(size_t)DIM1 * 8];
__device__ uint4 g_VTh[(size_t)DIM2 * 8];
__device__ int   g_x_is_i64;   // 1 if x is int64 (lo/hi pairs), 0 if int32

// ---------------------------------------------------------------------------
// Kernel 1: transpose + fp32->bf16 convert. (64 x DIM) -> (DIM x 64) bf16.
// Source loads use __ldcs (streaming / evict-first) so the 51.2MB fp32 read
// stream does NOT evict the 25.6MB bf16 table we are writing — the gather
// kernel then finds the table L2-resident instead of re-reading it from DRAM.
// Thread 0 of block 0 also probes the x dtype.
// ---------------------------------------------------------------------------
__global__ void __launch_bounds__(512)
transpose_convert_kernel(const float* __restrict__ U_w,
                         const float* __restrict__ V_w,
                         const int* __restrict__ xw) {
    __shared__ float tile[64][33];

    if (blockIdx.x == 0 && blockIdx.z == 0 &&
        threadIdx.x == 0 && threadIdx.y == 0) {
        int all_zero = 1;
        #pragma unroll
        for (int k = 0; k < 32; ++k)
            if (xw[2 * k + 1] != 0) all_zero = 0;
        g_x_is_i64 = all_zero;
    }

    const float*      src = (blockIdx.z == 0) ? U_w : V_w;
    __nv_bfloat162*   dst = (__nv_bfloat162*)((blockIdx.z == 0) ? g_UTh : g_VTh);

    int c0 = blockIdx.x * 32;                 // DIM offset; DIM1 % 32 == 0
    int tx = threadIdx.x, ty = threadIdx.y;

    #pragma unroll
    for (int j = 0; j < 4; ++j) {
        int r = ty + 16 * j;                  // 0..63
        tile[r][tx] = __ldcs(&src[(size_t)r * DIM1 + (c0 + tx)]);
    }
    __syncthreads();

    #pragma unroll
    for (int j = 0; j < 2; ++j) {
        int c = ty + 16 * j;                  // 0..31
        float lo = tile[2 * tx][c];
        float hi = tile[2 * tx + 1][c];
        dst[(size_t)(c0 + c) * 32 + tx] = __floats2bfloat162_rn(lo, hi);
    }
}

// 8-term bf16 dot accumulated in fp32.
__device__ __forceinline__ float dot8(uint4 a, uint4 b) {
    const __nv_bfloat162* pa = (const __nv_bfloat162*)&a;
    const __nv_bfloat162* pb = (const __nv_bfloat162*)&b;
    float s = 0.0f;
    #pragma unroll
    for (int k = 0; k < 4; ++k) {
        float2 fa = __bfloat1622float2(pa[k]);
        float2 fb = __bfloat1622float2(pb[k]);
        s += fa.x * fb.x + fa.y * fb.y;
    }
    return s;
}

// ---------------------------------------------------------------------------
// Kernel 2 (R4-proven shape): gather + rank-64 dot. 4 lanes per batch
// element; each lane loads 2 uint4 (32B) from each 128B table row -> MLP 4
// at 32 regs (the sweet spot ptxas will actually keep live). One int4 index
// load per group. Biases on lanes 0/1, folded into the 2-deep shfl tree.
// ---------------------------------------------------------------------------
__global__ void __launch_bounds__(256)
gather_dot_kernel(const int* __restrict__ xw,
                  const float* __restrict__ bias_U,
                  const float* __restrict__ bias_V,
                  float* __restrict__ out) {
    int gid  = blockIdx.x * blockDim.x + threadIdx.x;
    int b    = gid >> 2;        // 4 lanes per element
    int lane = gid & 3;
    if (b >= BATCH) return;

    int i1, i2;
    if (g_x_is_i64) {           // int64 pairs: one 16B load covers both
        int4 p = __ldg((const int4*)xw + b);
        i1 = p.x;
        i2 = p.z;
    } else {                    // int32 pairs
        int2 p = __ldg((const int2*)xw + b);
        i1 = p.x;
        i2 = p.y;
    }

    const uint4* u = g_UTh + (size_t)i1 * 8 + 2 * lane;
    const uint4* v = g_VTh + (size_t)i2 * 8 + 2 * lane;

    uint4 a0 = __ldg(u);
    uint4 a1 = __ldg(u + 1);
    uint4 c0 = __ldg(v);
    uint4 c1 = __ldg(v + 1);

    float bias = 0.0f;
    if (lane == 0) bias = __ldg(bias_U + i1);
    if (lane == 1) bias = __ldg(bias_V + i2);

    float s = dot8(a0, c0) + dot8(a1, c1) + bias;

    // Reduce across the 4-lane group (biases ride along).
    s += __shfl_xor_sync(0xffffffffu, s, 2);
    s += __shfl_xor_sync(0xffffffffu, s, 1);

    if (lane == 0) out[b] = s;
}

// ---------------------------------------------------------------------------
// kernel_launch: transpose+convert (+probe), then gather. Two launches,
// no sync, no allocation, graph-capturable.
// Input order: x, U_w(f32, RANK*DIM1), V_w(f32, RANK*DIM2), bias_U, bias_V
// ---------------------------------------------------------------------------
extern "C" void kernel_launch(void* const* d_in, const int* in_sizes, int n_in,
                              void* d_out, int out_size) {
    const int*   xw     = (const int*)d_in[0];
    const float* U_w    = (const float*)d_in[1];
    const float* V_w    = (const float*)d_in[2];
    const float* bias_U = (const float*)d_in[3];
    const float* bias_V = (const float*)d_in[4];
    float*       out    = (float*)d_out;

    dim3 tgrid(DIM1 / 32, 1, 2);
    dim3 tblock(32, 16, 1);
    transpose_convert_kernel<<<tgrid, tblock>>>(U_w, V_w, xw);

    int total_threads = BATCH * 4;
    int block = 256;
    int grid  = (total_threads + block - 1) / block;
    gather_dot_kernel<<<grid, block>>>(xw, bias_U, bias_V, out);
}